// round 3
// baseline (speedup 1.0000x reference)
#include <cuda_runtime.h>

#define B_  2
#define DD  64
#define HH  256
#define WW  256
#define HW  (HH*WW)
#define DHW (DD*HW)
#define PD  (DD+2)
#define PH  (HH+2)
#define PW  (WW+2)
#define PHW (PH*PW)      // 66564

// Zero-padded moving channel (channel 0), per batch. 2 * 4.39M * 4B = 35.1 MB.
__device__ float g_xpad[B_ * PD * PHW];

// ---------------------------------------------------------------------------
// Kernel 1: build the padded moving image (x[:, 0] padded by 1 on each side).
// ---------------------------------------------------------------------------
__global__ void __launch_bounds__(256) pad_kernel(const float* __restrict__ x) {
    int i = blockIdx.x * 256 + threadIdx.x;
    const int total = B_ * PD * PHW;
    if (i >= total) return;
    int b = i / (PD * PHW);
    int r = i - b * (PD * PHW);
    int z = r / PHW; r -= z * PHW;
    int y = r / PW;
    int xx = r - y * PW;
    float v = 0.f;
    if ((unsigned)(z - 1) < (unsigned)DD &&
        (unsigned)(y - 1) < (unsigned)HH &&
        (unsigned)(xx - 1) < (unsigned)WW) {
        v = x[(size_t)b * 2 * DHW + (size_t)(z - 1) * HW + (y - 1) * WW + (xx - 1)];
    }
    g_xpad[i] = v;
}

// ---------------------------------------------------------------------------
// Kernel 2: fused offset-conv + trilinear deformable sampling + fixed copy.
// Conv emulates XLA:CPU ConvolutionThunk -> Eigen CuboidConvolution:
//   per-output sequential reduction, ascending k = c + 2*(kx + 3*(ky + 3*kz)),
//   single accumulator, FUSED multiply-add (fmaf), acc starts at 0,
//   bias added afterwards as a separate fp32 add.
// Downstream elementwise math is op-for-op faithful (__f*_rn, no contraction).
// ---------------------------------------------------------------------------
__global__ void __launch_bounds__(256) reg3d_kernel(
    const float* __restrict__ x,
    const float* __restrict__ wp,   // [3, 2, 3, 3, 3]
    const float* __restrict__ bp,   // [3]
    float* __restrict__ out)        // [2, 2, 64, 256, 256]
{
    __shared__ float sw[162];
    __shared__ float sb[3];
    int t = threadIdx.x;
    if (t < 162) sw[t] = wp[t];
    if (t < 3)   sb[t] = bp[t];
    __syncthreads();

    int linear = blockIdx.x * 256 + t;        // 2^21 threads total
    int xt = linear & 63;                     // x-quad index (0..63)
    int y  = (linear >> 6)  & 255;
    int z  = (linear >> 14) & 63;
    int b  = linear >> 20;                    // 0..1

    const float* xb = x + (size_t)b * 2 * DHW;

    // ---- conv: 3 output channels, 4 x-positions ----
    float a0[4], a1[4], a2[4];
    #pragma unroll
    for (int j = 0; j < 4; j++) { a0[j] = 0.f; a1[j] = 0.f; a2[j] = 0.f; }

    int x0 = (xt << 2) - 1;   // leftmost halo x
    #pragma unroll
    for (int kz = 0; kz < 3; kz++) {
        int zz = z + kz - 1;
        bool zok = (unsigned)zz < (unsigned)DD;
        #pragma unroll
        for (int ky = 0; ky < 3; ky++) {
            int yy = y + ky - 1;
            bool yok = zok && ((unsigned)yy < (unsigned)HH);
            // load halo rows for both input channels (zeros outside)
            float v[2][6];
            #pragma unroll
            for (int c = 0; c < 2; c++) {
                const float* row = xb + (size_t)c * DHW + (size_t)zz * HW + yy * WW;
                #pragma unroll
                for (int j = 0; j < 6; j++) {
                    int xx = x0 + j;
                    v[c][j] = (yok && (unsigned)xx < (unsigned)WW)
                                  ? __ldg(row + xx) : 0.f;
                }
            }
            const float* wr = sw + kz * 9 + ky * 3;   // out-ch 0, in-ch 0 base
            #pragma unroll
            for (int kx = 0; kx < 3; kx++) {
                // ascending k: channel innermost, FMA accumulation
                #pragma unroll
                for (int c = 0; c < 2; c++) {
                    float w0 = wr[c * 27 + kx];
                    float w1 = wr[54  + c * 27 + kx];
                    float w2 = wr[108 + c * 27 + kx];
                    #pragma unroll
                    for (int j = 0; j < 4; j++) {
                        a0[j] = __fmaf_rn(v[c][kx + j], w0, a0[j]);
                        a1[j] = __fmaf_rn(v[c][kx + j], w1, a1[j]);
                        a2[j] = __fmaf_rn(v[c][kx + j], w2, a2[j]);
                    }
                }
            }
        }
    }

    // ---- sampling ----
    const float* xpad = g_xpad + (size_t)b * PD * PHW;
    size_t obase = (size_t)b * 2 * DHW + (size_t)z * HW + (size_t)y * WW + (xt << 2);
    float res[4];

    #pragma unroll
    for (int j = 0; j < 4; j++) {
        int xi = (xt << 2) + j;
        float oz = __fadd_rn(a0[j], sb[0]);
        float oy = __fadd_rn(a1[j], sb[1]);
        float ox = __fadd_rn(a2[j], sb[2]);

        float qz = fminf(fmaxf(__fadd_rn((float)(z + 1), oz), 0.f), 64.f);
        float qy = fminf(fmaxf(__fadd_rn((float)(y + 1), oy), 0.f), 256.f);
        float qx = fminf(fmaxf(__fadd_rn((float)(xi + 1), ox), 0.f), 256.f);

        float lz = __fadd_rn(qz, -floorf(qz));
        float ly = __fadd_rn(qy, -floorf(qy));
        float lx = __fadd_rn(qx, -floorf(qx));
        float wz0 = __fadd_rn(1.f, -lz);
        float wy0 = __fadd_rn(1.f, -ly);
        float wx0 = __fadd_rn(1.f, -lx);

        float acc = 0.f;
        #pragma unroll
        for (int dz = 0; dz < 2; dz++) {
            float cz = __fadd_rn(qz, (float)dz);
            float wz = dz ? lz : wz0;
            float czp = __fmul_rn(cz, (float)PHW);
            #pragma unroll
            for (int dy = 0; dy < 2; dy++) {
                float cy  = __fadd_rn(qy, (float)dy);
                float wzy = __fmul_rn(wz, dy ? ly : wy0);
                float czyp = __fadd_rn(czp, __fmul_rn(cy, (float)PW));
                #pragma unroll
                for (int dx = 0; dx < 2; dx++) {
                    float cx   = __fadd_rn(qx, (float)dx);
                    float comb = __fadd_rn(czyp, cx);
                    unsigned idx = (unsigned)comb;   // trunc toward zero (astype int32)
                    float wv = __fmul_rn(wzy, dx ? lx : wx0);
                    acc = __fadd_rn(acc, __fmul_rn(__ldg(xpad + idx), wv));
                }
            }
        }
        res[j] = acc;
    }

    // channel 0: deformed moving image; channel 1: fixed image copy
    *reinterpret_cast<float4*>(out + obase) =
        make_float4(res[0], res[1], res[2], res[3]);
    const float4 fix = *reinterpret_cast<const float4*>(
        xb + DHW + (size_t)z * HW + (size_t)y * WW + (xt << 2));
    *reinterpret_cast<float4*>(out + obase + DHW) = fix;
}

// ---------------------------------------------------------------------------
extern "C" void kernel_launch(void* const* d_in, const int* in_sizes, int n_in,
                              void* d_out, int out_size) {
    const float* x  = (const float*)d_in[0];
    const float* wp = (const float*)d_in[1];
    const float* bp = (const float*)d_in[2];
    float* out = (float*)d_out;

    const int pad_total = B_ * PD * PHW;
    pad_kernel<<<(pad_total + 255) / 256, 256>>>(x);

    // 2 * 64 * 256 * 64 = 2^21 threads -> 8192 blocks of 256
    reg3d_kernel<<<8192, 256>>>(x, wp, bp, out);
}